// round 1
// baseline (speedup 1.0000x reference)
#include <cuda_runtime.h>

#define B_  4
#define C_  256
#define CQ_ 32
#define N_  4096
#define HW_ 64

// ---------------- scratch (device globals; no allocation) ----------------
__device__ float g_q[B_ * CQ_ * N_];
__device__ float g_k[B_ * CQ_ * N_];
__device__ float g_v[B_ * C_ * N_];
__device__ float g_attn[(size_t)B_ * N_ * N_];      // 256 MB
__device__ float g_cat[(size_t)B_ * 2 * C_ * N_];   // [b][512][4096]
__device__ float g_cattn[B_ * C_ * C_];
__device__ float g_y[(size_t)B_ * C_ * N_];
__device__ float g_mean[C_];
__device__ float g_rstd[C_];

// ---------------- helpers ----------------
__device__ __forceinline__ float warpMax(float v) {
    #pragma unroll
    for (int o = 16; o; o >>= 1) v = fmaxf(v, __shfl_xor_sync(0xffffffffu, v, o));
    return v;
}
__device__ __forceinline__ float warpSum(float v) {
    #pragma unroll
    for (int o = 16; o; o >>= 1) v += __shfl_xor_sync(0xffffffffu, v, o);
    return v;
}

// 64x64 tile compute: acc[4][4] += As[k][m] * Bs[k][n]
__device__ __forceinline__ void mma_tile(const float (*As)[64], const float (*Bs)[64],
                                         float acc[4][4], int ty, int tx) {
    #pragma unroll
    for (int k = 0; k < 16; k++) {
        float4 a = *(const float4*)&As[k][ty * 4];
        float4 b = *(const float4*)&Bs[k][tx * 4];
        float ar[4] = {a.x, a.y, a.z, a.w};
        float br[4] = {b.x, b.y, b.z, b.w};
        #pragma unroll
        for (int i = 0; i < 4; i++)
            #pragma unroll
            for (int j = 0; j < 4; j++)
                acc[i][j] = fmaf(ar[i], br[j], acc[i][j]);
    }
}

// epi: 0 -> +bias[m]; 1 -> gamma*acc + res[m*N+n]; 2 -> raw
__device__ __forceinline__ void epilogue(float* Out, int M, int N, int m0, int n0,
                                         int ty, int tx, float acc[4][4], int epi,
                                         const float* bias, const float* gsc,
                                         const float* res) {
    float g = gsc ? *gsc : 0.f;
    #pragma unroll
    for (int i = 0; i < 4; i++) {
        int m = m0 + ty * 4 + i;
        if (m < M) {
            long off = (long)m * N + n0 + tx * 4;
            float4 o;
            if (epi == 0) {
                float bv = bias[m];
                o = make_float4(acc[i][0] + bv, acc[i][1] + bv, acc[i][2] + bv, acc[i][3] + bv);
            } else if (epi == 1) {
                float4 r = *(const float4*)(res + off);
                o = make_float4(fmaf(g, acc[i][0], r.x), fmaf(g, acc[i][1], r.y),
                                fmaf(g, acc[i][2], r.z), fmaf(g, acc[i][3], r.w));
            } else {
                o = make_float4(acc[i][0], acc[i][1], acc[i][2], acc[i][3]);
            }
            *(float4*)(Out + off) = o;
        }
    }
}

// ---------------- GEMM kernels (BM=BN=64, BK=16, 256 threads, 4x4 microtile) ----------------

// Out[m][n] = sum_k A[m][k] * B[k][n]   (A: MxK row-major; B: KxN, n contiguous)
__global__ void gemm_nn_k(const float* __restrict__ A, const float* __restrict__ Bm,
                          float* __restrict__ Out, int M, int N, int K, int epi,
                          const float* __restrict__ bias, const float* __restrict__ gsc,
                          const float* __restrict__ res,
                          long sA, long sB, long sO, long sR) {
    int b = blockIdx.z;
    A += sA * b; Bm += sB * b; Out += sO * b;
    const float* resb = res ? res + sR * b : nullptr;
    __shared__ float As[16][64];
    __shared__ float Bs[16][64];
    int tid = threadIdx.x;
    int tx = tid & 15, ty = tid >> 4;
    int m0 = blockIdx.y * 64, n0 = blockIdx.x * 64;
    int arow = tid >> 2, ak = (tid & 3) * 4;
    int brow = tid >> 4, bn = (tid & 15) * 4;
    float acc[4][4] = {};
    for (int k0 = 0; k0 < K; k0 += 16) {
        float4 av = make_float4(0.f, 0.f, 0.f, 0.f);
        if (m0 + arow < M) av = *(const float4*)(A + (long)(m0 + arow) * K + k0 + ak);
        As[ak + 0][arow] = av.x; As[ak + 1][arow] = av.y;
        As[ak + 2][arow] = av.z; As[ak + 3][arow] = av.w;
        *(float4*)&Bs[brow][bn] = *(const float4*)(Bm + (long)(k0 + brow) * N + n0 + bn);
        __syncthreads();
        mma_tile(As, Bs, acc, ty, tx);
        __syncthreads();
    }
    epilogue(Out, M, N, m0, n0, ty, tx, acc, epi, bias, gsc, resb);
}

// Out[m][n] = sum_k A[m][k] * B[n][k]   (both K-contiguous)
__global__ void gemm_nt_k(const float* __restrict__ A, const float* __restrict__ Bm,
                          float* __restrict__ Out, int M, int N, int K, int epi,
                          const float* __restrict__ bias, const float* __restrict__ gsc,
                          const float* __restrict__ res,
                          long sA, long sB, long sO, long sR) {
    int b = blockIdx.z;
    A += sA * b; Bm += sB * b; Out += sO * b;
    const float* resb = res ? res + sR * b : nullptr;
    __shared__ float As[16][64];
    __shared__ float Bs[16][64];
    int tid = threadIdx.x;
    int tx = tid & 15, ty = tid >> 4;
    int m0 = blockIdx.y * 64, n0 = blockIdx.x * 64;
    int arow = tid >> 2, ak = (tid & 3) * 4;
    float acc[4][4] = {};
    for (int k0 = 0; k0 < K; k0 += 16) {
        float4 av = make_float4(0.f, 0.f, 0.f, 0.f);
        if (m0 + arow < M) av = *(const float4*)(A + (long)(m0 + arow) * K + k0 + ak);
        As[ak + 0][arow] = av.x; As[ak + 1][arow] = av.y;
        As[ak + 2][arow] = av.z; As[ak + 3][arow] = av.w;
        float4 bv = *(const float4*)(Bm + (long)(n0 + arow) * K + k0 + ak);
        Bs[ak + 0][arow] = bv.x; Bs[ak + 1][arow] = bv.y;
        Bs[ak + 2][arow] = bv.z; Bs[ak + 3][arow] = bv.w;
        __syncthreads();
        mma_tile(As, Bs, acc, ty, tx);
        __syncthreads();
    }
    epilogue(Out, M, N, m0, n0, ty, tx, acc, epi, bias, gsc, resb);
}

// Out[m][n] = sum_k A[k][m] * B[k][n]   (A: KxM m-contig; B: KxN n-contig)
__global__ void gemm_tn_k(const float* __restrict__ A, const float* __restrict__ Bm,
                          float* __restrict__ Out, int M, int N, int K, int epi,
                          const float* __restrict__ bias, const float* __restrict__ gsc,
                          const float* __restrict__ res,
                          long sA, long sB, long sO, long sR) {
    int b = blockIdx.z;
    A += sA * b; Bm += sB * b; Out += sO * b;
    const float* resb = res ? res + sR * b : nullptr;
    __shared__ float As[16][64];
    __shared__ float Bs[16][64];
    int tid = threadIdx.x;
    int tx = tid & 15, ty = tid >> 4;
    int m0 = blockIdx.y * 64, n0 = blockIdx.x * 64;
    int krow = tid >> 4, c4 = (tid & 15) * 4;
    float acc[4][4] = {};
    for (int k0 = 0; k0 < K; k0 += 16) {
        *(float4*)&As[krow][c4] = *(const float4*)(A + (long)(k0 + krow) * M + m0 + c4);
        *(float4*)&Bs[krow][c4] = *(const float4*)(Bm + (long)(k0 + krow) * N + n0 + c4);
        __syncthreads();
        mma_tile(As, Bs, acc, ty, tx);
        __syncthreads();
    }
    epilogue(Out, M, N, m0, n0, ty, tx, acc, epi, bias, gsc, resb);
}

// ---------------- softmax ----------------
__global__ void softmax4096(float* __restrict__ data) {
    __shared__ float sh[8];
    float4* p = (float4*)(data + (size_t)blockIdx.x * 4096);
    int tid = threadIdx.x;
    float4 v[4];
    #pragma unroll
    for (int j = 0; j < 4; j++) v[j] = p[tid + 256 * j];
    float m = -3e38f;
    #pragma unroll
    for (int j = 0; j < 4; j++) {
        m = fmaxf(m, fmaxf(fmaxf(v[j].x, v[j].y), fmaxf(v[j].z, v[j].w)));
    }
    m = warpMax(m);
    if ((tid & 31) == 0) sh[tid >> 5] = m;
    __syncthreads();
    m = sh[tid & 7];
    #pragma unroll
    for (int o = 4; o; o >>= 1) m = fmaxf(m, __shfl_xor_sync(0xffffffffu, m, o));
    __syncthreads();
    float s = 0.f;
    #pragma unroll
    for (int j = 0; j < 4; j++) {
        v[j].x = __expf(v[j].x - m); v[j].y = __expf(v[j].y - m);
        v[j].z = __expf(v[j].z - m); v[j].w = __expf(v[j].w - m);
        s += v[j].x + v[j].y + v[j].z + v[j].w;
    }
    s = warpSum(s);
    if ((tid & 31) == 0) sh[tid >> 5] = s;
    __syncthreads();
    s = sh[tid & 7];
    #pragma unroll
    for (int o = 4; o; o >>= 1) s += __shfl_xor_sync(0xffffffffu, s, o);
    float inv = 1.f / s;
    #pragma unroll
    for (int j = 0; j < 4; j++) {
        v[j].x *= inv; v[j].y *= inv; v[j].z *= inv; v[j].w *= inv;
        p[tid + 256 * j] = v[j];
    }
}

__global__ void softmax256(float* __restrict__ data) {
    __shared__ float sh[8];
    float* p = data + (size_t)blockIdx.x * 256;
    int tid = threadIdx.x;
    float v = p[tid];
    float m = warpMax(v);
    if ((tid & 31) == 0) sh[tid >> 5] = m;
    __syncthreads();
    m = sh[tid & 7];
    #pragma unroll
    for (int o = 4; o; o >>= 1) m = fmaxf(m, __shfl_xor_sync(0xffffffffu, m, o));
    __syncthreads();
    float e = __expf(v - m);
    float s = warpSum(e);
    if ((tid & 31) == 0) sh[tid >> 5] = s;
    __syncthreads();
    s = sh[tid & 7];
    #pragma unroll
    for (int o = 4; o; o >>= 1) s += __shfl_xor_sync(0xffffffffu, s, o);
    p[tid] = e / s;
}

// ---------------- 3x3 conv, 512 -> 256, pad 1 ----------------
// grid: (4 o-tiles, 64 h, 4 b); block 256. Each block: y[b, o0:o0+64, h, 0:64]
__global__ void conv3x3(const float* __restrict__ cat, const float* __restrict__ wf,
                        float* __restrict__ y) {
    __shared__ float xs[8][3][66];
    __shared__ float ws[8][9][64];
    int b = blockIdx.z, h = blockIdx.y, o0 = blockIdx.x * 64;
    int tid = threadIdx.x;
    int tx = tid & 15, ty = tid >> 4;   // w-micro = tx*4, o-micro = ty*4
    float acc[4][4] = {};               // [o][w]
    for (int c0 = 0; c0 < 512; c0 += 8) {
        // input patch: 8 ci x 3 rows x 64 w (with zero halo in w)
        for (int idx = tid; idx < 8 * 3 * 64; idx += 256) {
            int ci = idx / 192;
            int r = (idx / 64) % 3;
            int w = idx % 64;
            int hh = h + r - 1;
            float val = 0.f;
            if (hh >= 0 && hh < 64)
                val = cat[((long)b * 512 + c0 + ci) * 4096 + hh * 64 + w];
            xs[ci][r][w + 1] = val;
        }
        if (tid < 24) {
            int ci = tid / 3, r = tid % 3;
            xs[ci][r][0] = 0.f; xs[ci][r][65] = 0.f;
        }
        // weights: ws[ci][khkw][o]
        for (int idx = tid; idx < 8 * 9 * 64; idx += 256) {
            int o = idx / 72;
            int r = idx % 72;
            int ci = r / 9, kk = r % 9;
            ws[ci][kk][o] = wf[(long)(o0 + o) * 4608 + (c0 + ci) * 9 + kk];
        }
        __syncthreads();
        #pragma unroll
        for (int ci = 0; ci < 8; ci++) {
            #pragma unroll
            for (int kh = 0; kh < 3; kh++) {
                float xv[6];
                #pragma unroll
                for (int t = 0; t < 6; t++) xv[t] = xs[ci][kh][tx * 4 + t];
                #pragma unroll
                for (int kw = 0; kw < 3; kw++) {
                    float4 wv = *(const float4*)&ws[ci][kh * 3 + kw][ty * 4];
                    float wr[4] = {wv.x, wv.y, wv.z, wv.w};
                    #pragma unroll
                    for (int i = 0; i < 4; i++)
                        #pragma unroll
                        for (int j = 0; j < 4; j++)
                            acc[i][j] = fmaf(wr[i], xv[kw + j], acc[i][j]);
                }
            }
        }
        __syncthreads();
    }
    #pragma unroll
    for (int i = 0; i < 4; i++) {
        long off = ((long)b * 256 + o0 + ty * 4 + i) * 4096 + h * 64 + tx * 4;
        *(float4*)(y + off) = make_float4(acc[i][0], acc[i][1], acc[i][2], acc[i][3]);
    }
}

// ---------------- BN (train-mode batch stats) + ReLU ----------------
__global__ void bnstats(const float* __restrict__ y, float* __restrict__ meanp,
                        float* __restrict__ rstdp) {
    __shared__ float sh[16];
    int o = blockIdx.x, tid = threadIdx.x;
    float s = 0.f, sq = 0.f;
    for (int b = 0; b < 4; b++) {
        const float4* p = (const float4*)(y + ((size_t)b * 256 + o) * 4096);
        for (int i = tid; i < 1024; i += 256) {
            float4 v = p[i];
            s += v.x + v.y + v.z + v.w;
            sq += v.x * v.x + v.y * v.y + v.z * v.z + v.w * v.w;
        }
    }
    s = warpSum(s); sq = warpSum(sq);
    if ((tid & 31) == 0) { sh[tid >> 5] = s; sh[8 + (tid >> 5)] = sq; }
    __syncthreads();
    if (tid == 0) {
        float S = 0.f, SQ = 0.f;
        for (int i = 0; i < 8; i++) { S += sh[i]; SQ += sh[8 + i]; }
        float mean = S / 16384.f;
        float var = SQ / 16384.f - mean * mean;
        meanp[o] = mean;
        rstdp[o] = rsqrtf(var + 1e-5f);
    }
}

__global__ void bnapply(const float* __restrict__ y, const float* __restrict__ gam,
                        const float* __restrict__ bet, const float* __restrict__ meanp,
                        const float* __restrict__ rstdp, float* __restrict__ out) {
    size_t i = (size_t)blockIdx.x * 256 + threadIdx.x;  // float4 index
    int o = (int)((i >> 10) & 255);
    float mu = meanp[o], rs = rstdp[o], g = gam[o], be = bet[o];
    float4 v = ((const float4*)y)[i];
    float4 r;
    r.x = fmaxf(0.f, fmaf((v.x - mu) * rs, g, be));
    r.y = fmaxf(0.f, fmaf((v.y - mu) * rs, g, be));
    r.z = fmaxf(0.f, fmaf((v.z - mu) * rs, g, be));
    r.w = fmaxf(0.f, fmaf((v.w - mu) * rs, g, be));
    ((float4*)out)[i] = r;
}

// ---------------- launcher ----------------
extern "C" void kernel_launch(void* const* d_in, const int* in_sizes, int n_in,
                              void* d_out, int out_size) {
    const float* x   = (const float*)d_in[0];
    const float* wq  = (const float*)d_in[1];
    const float* bq  = (const float*)d_in[2];
    const float* wk  = (const float*)d_in[3];
    const float* bk  = (const float*)d_in[4];
    const float* wv  = (const float*)d_in[5];
    const float* bv  = (const float*)d_in[6];
    const float* gpa = (const float*)d_in[7];
    const float* gca = (const float*)d_in[8];
    const float* wf  = (const float*)d_in[9];
    const float* bng = (const float*)d_in[10];
    const float* bnb = (const float*)d_in[11];
    float* out = (float*)d_out;

    float *q, *k, *v, *attn, *cat, *cattn, *y, *mean, *rstd;
    cudaGetSymbolAddress((void**)&q, g_q);
    cudaGetSymbolAddress((void**)&k, g_k);
    cudaGetSymbolAddress((void**)&v, g_v);
    cudaGetSymbolAddress((void**)&attn, g_attn);
    cudaGetSymbolAddress((void**)&cat, g_cat);
    cudaGetSymbolAddress((void**)&cattn, g_cattn);
    cudaGetSymbolAddress((void**)&y, g_y);
    cudaGetSymbolAddress((void**)&mean, g_mean);
    cudaGetSymbolAddress((void**)&rstd, g_rstd);

    dim3 blk(256);
    long sx = (long)C_ * N_;           // 1,048,576
    long sqk = (long)CQ_ * N_;
    long sattn = (long)N_ * N_;
    long scat = (long)2 * C_ * N_;

    // q, k, v projections (1x1 convs as GEMMs)
    gemm_nn_k<<<dim3(64, 1, 4), blk>>>(wq, x, q, CQ_, N_, C_, 0, bq, nullptr, nullptr,
                                       0, sx, sqk, 0);
    gemm_nn_k<<<dim3(64, 1, 4), blk>>>(wk, x, k, CQ_, N_, C_, 0, bk, nullptr, nullptr,
                                       0, sx, sqk, 0);
    gemm_nn_k<<<dim3(64, 4, 4), blk>>>(wv, x, v, C_, N_, C_, 0, bv, nullptr, nullptr,
                                       0, sx, sx, 0);
    // logits[i][j] = sum_d q[d][i] k[d][j]
    gemm_tn_k<<<dim3(64, 64, 4), blk>>>(q, k, attn, N_, N_, CQ_, 2, nullptr, nullptr,
                                        nullptr, sqk, sqk, sattn, 0);
    softmax4096<<<B_ * N_, 256>>>(attn);
    // pa[c][i] = gamma_pa * sum_j v[c][j] attn[i][j] + x[c][i]  -> cat[:, 0:256]
    gemm_nt_k<<<dim3(64, 4, 4), blk>>>(v, attn, cat, C_, N_, N_, 1, nullptr, gpa, x,
                                       sx, sattn, scat, sx);
    // channel logits[i][j] = sum_n x[i][n] x[j][n]
    gemm_nt_k<<<dim3(4, 4, 4), blk>>>(x, x, cattn, C_, C_, N_, 2, nullptr, nullptr,
                                      nullptr, sx, sx, (long)C_ * C_, 0);
    softmax256<<<B_ * C_, 256>>>(cattn);
    // ca[i][n] = gamma_ca * sum_j cattn[i][j] x[j][n] + x[i][n]  -> cat[:, 256:512]
    gemm_nn_k<<<dim3(64, 4, 4), blk>>>(cattn, x, cat + (size_t)C_ * N_, C_, N_, C_, 1,
                                       nullptr, gca, x, (long)C_ * C_, sx, scat, sx);
    // 3x3 conv 512->256
    conv3x3<<<dim3(4, 64, 4), blk>>>(cat, wf, y);
    // BN train-mode + ReLU
    bnstats<<<256, 256>>>(y, mean, rstd);
    bnapply<<<4096, 256>>>(y, bng, bnb, mean, rstd, out);
}

// round 2
// speedup vs baseline: 1.0017x; 1.0017x over previous
#include <cuda_runtime.h>

#define B_  4
#define C_  256
#define CQ_ 32
#define N_  4096
#define HW_ 64

// ---------------- scratch (device globals; no allocation) ----------------
__device__ float g_q[B_ * CQ_ * N_];
__device__ float g_k[B_ * CQ_ * N_];
__device__ float g_v[B_ * C_ * N_];
__device__ float g_attn[(size_t)B_ * N_ * N_];      // 256 MB
__device__ float g_cat[(size_t)B_ * 2 * C_ * N_];   // [b][512][4096]
__device__ float g_cattn[B_ * C_ * C_];
__device__ float g_y[(size_t)B_ * C_ * N_];
__device__ float g_mean[C_];
__device__ float g_rstd[C_];

// ---------------- helpers ----------------
__device__ __forceinline__ float warpMax(float v) {
    #pragma unroll
    for (int o = 16; o; o >>= 1) v = fmaxf(v, __shfl_xor_sync(0xffffffffu, v, o));
    return v;
}
__device__ __forceinline__ float warpSum(float v) {
    #pragma unroll
    for (int o = 16; o; o >>= 1) v += __shfl_xor_sync(0xffffffffu, v, o);
    return v;
}

// 64x64 tile compute: acc[4][4] += As[k][m] * Bs[k][n]
__device__ __forceinline__ void mma_tile(const float (*As)[64], const float (*Bs)[64],
                                         float acc[4][4], int ty, int tx) {
    #pragma unroll
    for (int k = 0; k < 16; k++) {
        float4 a = *(const float4*)&As[k][ty * 4];
        float4 b = *(const float4*)&Bs[k][tx * 4];
        float ar[4] = {a.x, a.y, a.z, a.w};
        float br[4] = {b.x, b.y, b.z, b.w};
        #pragma unroll
        for (int i = 0; i < 4; i++)
            #pragma unroll
            for (int j = 0; j < 4; j++)
                acc[i][j] = fmaf(ar[i], br[j], acc[i][j]);
    }
}

// epi: 0 -> +bias[m]; 1 -> gamma*acc + res[m*N+n]; 2 -> raw
__device__ __forceinline__ void epilogue(float* Out, int M, int N, int m0, int n0,
                                         int ty, int tx, float acc[4][4], int epi,
                                         const float* bias, const float* gsc,
                                         const float* res) {
    float g = gsc ? *gsc : 0.f;
    #pragma unroll
    for (int i = 0; i < 4; i++) {
        int m = m0 + ty * 4 + i;
        if (m < M) {
            long off = (long)m * N + n0 + tx * 4;
            float4 o;
            if (epi == 0) {
                float bv = bias[m];
                o = make_float4(acc[i][0] + bv, acc[i][1] + bv, acc[i][2] + bv, acc[i][3] + bv);
            } else if (epi == 1) {
                float4 r = *(const float4*)(res + off);
                o = make_float4(fmaf(g, acc[i][0], r.x), fmaf(g, acc[i][1], r.y),
                                fmaf(g, acc[i][2], r.z), fmaf(g, acc[i][3], r.w));
            } else {
                o = make_float4(acc[i][0], acc[i][1], acc[i][2], acc[i][3]);
            }
            *(float4*)(Out + off) = o;
        }
    }
}

// ---------------- GEMM kernels (BM=BN=64, BK=16, 256 threads, 4x4 microtile) ----------------

// Out[m][n] = sum_k A[m][k] * B[k][n]   (A: MxK row-major; B: KxN, n contiguous)
__global__ void gemm_nn_k(const float* __restrict__ A, const float* __restrict__ Bm,
                          float* __restrict__ Out, int M, int N, int K, int epi,
                          const float* __restrict__ bias, const float* __restrict__ gsc,
                          const float* __restrict__ res,
                          long sA, long sB, long sO, long sR) {
    int b = blockIdx.z;
    A += sA * b; Bm += sB * b; Out += sO * b;
    const float* resb = res ? res + sR * b : nullptr;
    __shared__ float As[16][64];
    __shared__ float Bs[16][64];
    int tid = threadIdx.x;
    int tx = tid & 15, ty = tid >> 4;
    int m0 = blockIdx.y * 64, n0 = blockIdx.x * 64;
    int arow = tid >> 2, ak = (tid & 3) * 4;
    int brow = tid >> 4, bn = (tid & 15) * 4;
    float acc[4][4] = {};
    for (int k0 = 0; k0 < K; k0 += 16) {
        float4 av = make_float4(0.f, 0.f, 0.f, 0.f);
        if (m0 + arow < M) av = *(const float4*)(A + (long)(m0 + arow) * K + k0 + ak);
        As[ak + 0][arow] = av.x; As[ak + 1][arow] = av.y;
        As[ak + 2][arow] = av.z; As[ak + 3][arow] = av.w;
        *(float4*)&Bs[brow][bn] = *(const float4*)(Bm + (long)(k0 + brow) * N + n0 + bn);
        __syncthreads();
        mma_tile(As, Bs, acc, ty, tx);
        __syncthreads();
    }
    epilogue(Out, M, N, m0, n0, ty, tx, acc, epi, bias, gsc, resb);
}

// Out[m][n] = sum_k A[m][k] * B[n][k]   (both K-contiguous)
__global__ void gemm_nt_k(const float* __restrict__ A, const float* __restrict__ Bm,
                          float* __restrict__ Out, int M, int N, int K, int epi,
                          const float* __restrict__ bias, const float* __restrict__ gsc,
                          const float* __restrict__ res,
                          long sA, long sB, long sO, long sR) {
    int b = blockIdx.z;
    A += sA * b; Bm += sB * b; Out += sO * b;
    const float* resb = res ? res + sR * b : nullptr;
    __shared__ float As[16][64];
    __shared__ float Bs[16][64];
    int tid = threadIdx.x;
    int tx = tid & 15, ty = tid >> 4;
    int m0 = blockIdx.y * 64, n0 = blockIdx.x * 64;
    int arow = tid >> 2, ak = (tid & 3) * 4;
    float acc[4][4] = {};
    for (int k0 = 0; k0 < K; k0 += 16) {
        float4 av = make_float4(0.f, 0.f, 0.f, 0.f);
        if (m0 + arow < M) av = *(const float4*)(A + (long)(m0 + arow) * K + k0 + ak);
        As[ak + 0][arow] = av.x; As[ak + 1][arow] = av.y;
        As[ak + 2][arow] = av.z; As[ak + 3][arow] = av.w;
        float4 bv = *(const float4*)(Bm + (long)(n0 + arow) * K + k0 + ak);
        Bs[ak + 0][arow] = bv.x; Bs[ak + 1][arow] = bv.y;
        Bs[ak + 2][arow] = bv.z; Bs[ak + 3][arow] = bv.w;
        __syncthreads();
        mma_tile(As, Bs, acc, ty, tx);
        __syncthreads();
    }
    epilogue(Out, M, N, m0, n0, ty, tx, acc, epi, bias, gsc, resb);
}

// Out[m][n] = sum_k A[k][m] * B[k][n]   (A: KxM m-contig; B: KxN n-contig)
__global__ void gemm_tn_k(const float* __restrict__ A, const float* __restrict__ Bm,
                          float* __restrict__ Out, int M, int N, int K, int epi,
                          const float* __restrict__ bias, const float* __restrict__ gsc,
                          const float* __restrict__ res,
                          long sA, long sB, long sO, long sR) {
    int b = blockIdx.z;
    A += sA * b; Bm += sB * b; Out += sO * b;
    const float* resb = res ? res + sR * b : nullptr;
    __shared__ float As[16][64];
    __shared__ float Bs[16][64];
    int tid = threadIdx.x;
    int tx = tid & 15, ty = tid >> 4;
    int m0 = blockIdx.y * 64, n0 = blockIdx.x * 64;
    int krow = tid >> 4, c4 = (tid & 15) * 4;
    float acc[4][4] = {};
    for (int k0 = 0; k0 < K; k0 += 16) {
        *(float4*)&As[krow][c4] = *(const float4*)(A + (long)(k0 + krow) * M + m0 + c4);
        *(float4*)&Bs[krow][c4] = *(const float4*)(Bm + (long)(k0 + krow) * N + n0 + c4);
        __syncthreads();
        mma_tile(As, Bs, acc, ty, tx);
        __syncthreads();
    }
    epilogue(Out, M, N, m0, n0, ty, tx, acc, epi, bias, gsc, resb);
}

// ---------------- softmax ----------------
__global__ void softmax4096(float* __restrict__ data) {
    __shared__ float sh[8];
    float4* p = (float4*)(data + (size_t)blockIdx.x * 4096);
    int tid = threadIdx.x;
    float4 v[4];
    #pragma unroll
    for (int j = 0; j < 4; j++) v[j] = p[tid + 256 * j];
    float m = -3e38f;
    #pragma unroll
    for (int j = 0; j < 4; j++) {
        m = fmaxf(m, fmaxf(fmaxf(v[j].x, v[j].y), fmaxf(v[j].z, v[j].w)));
    }
    m = warpMax(m);
    if ((tid & 31) == 0) sh[tid >> 5] = m;
    __syncthreads();
    m = sh[tid & 7];
    #pragma unroll
    for (int o = 4; o; o >>= 1) m = fmaxf(m, __shfl_xor_sync(0xffffffffu, m, o));
    __syncthreads();
    float s = 0.f;
    #pragma unroll
    for (int j = 0; j < 4; j++) {
        v[j].x = __expf(v[j].x - m); v[j].y = __expf(v[j].y - m);
        v[j].z = __expf(v[j].z - m); v[j].w = __expf(v[j].w - m);
        s += v[j].x + v[j].y + v[j].z + v[j].w;
    }
    s = warpSum(s);
    if ((tid & 31) == 0) sh[tid >> 5] = s;
    __syncthreads();
    s = sh[tid & 7];
    #pragma unroll
    for (int o = 4; o; o >>= 1) s += __shfl_xor_sync(0xffffffffu, s, o);
    float inv = 1.f / s;
    #pragma unroll
    for (int j = 0; j < 4; j++) {
        v[j].x *= inv; v[j].y *= inv; v[j].z *= inv; v[j].w *= inv;
        p[tid + 256 * j] = v[j];
    }
}

__global__ void softmax256(float* __restrict__ data) {
    __shared__ float sh[8];
    float* p = data + (size_t)blockIdx.x * 256;
    int tid = threadIdx.x;
    float v = p[tid];
    float m = warpMax(v);
    if ((tid & 31) == 0) sh[tid >> 5] = m;
    __syncthreads();
    m = sh[tid & 7];
    #pragma unroll
    for (int o = 4; o; o >>= 1) m = fmaxf(m, __shfl_xor_sync(0xffffffffu, m, o));
    __syncthreads();
    float e = __expf(v - m);
    float s = warpSum(e);
    if ((tid & 31) == 0) sh[tid >> 5] = s;
    __syncthreads();
    s = sh[tid & 7];
    #pragma unroll
    for (int o = 4; o; o >>= 1) s += __shfl_xor_sync(0xffffffffu, s, o);
    p[tid] = e / s;
}

// ---------------- 3x3 conv, 512 -> 256, pad 1 ----------------
// grid: (4 o-tiles, 64 h, 4 b); block 256. Each block: y[b, o0:o0+64, h, 0:64]
__global__ void conv3x3(const float* __restrict__ cat, const float* __restrict__ wf,
                        float* __restrict__ y) {
    __shared__ float xs[8][3][66];
    __shared__ float ws[8][9][64];
    int b = blockIdx.z, h = blockIdx.y, o0 = blockIdx.x * 64;
    int tid = threadIdx.x;
    int tx = tid & 15, ty = tid >> 4;   // w-micro = tx*4, o-micro = ty*4
    float acc[4][4] = {};               // [o][w]
    for (int c0 = 0; c0 < 512; c0 += 8) {
        // input patch: 8 ci x 3 rows x 64 w (with zero halo in w)
        for (int idx = tid; idx < 8 * 3 * 64; idx += 256) {
            int ci = idx / 192;
            int r = (idx / 64) % 3;
            int w = idx % 64;
            int hh = h + r - 1;
            float val = 0.f;
            if (hh >= 0 && hh < 64)
                val = cat[((long)b * 512 + c0 + ci) * 4096 + hh * 64 + w];
            xs[ci][r][w + 1] = val;
        }
        if (tid < 24) {
            int ci = tid / 3, r = tid % 3;
            xs[ci][r][0] = 0.f; xs[ci][r][65] = 0.f;
        }
        // weights: ws[ci][khkw][o]
        for (int idx = tid; idx < 8 * 9 * 64; idx += 256) {
            int o = idx / 72;
            int r = idx % 72;
            int ci = r / 9, kk = r % 9;
            ws[ci][kk][o] = wf[(long)(o0 + o) * 4608 + (c0 + ci) * 9 + kk];
        }
        __syncthreads();
        #pragma unroll
        for (int ci = 0; ci < 8; ci++) {
            #pragma unroll
            for (int kh = 0; kh < 3; kh++) {
                float xv[6];
                #pragma unroll
                for (int t = 0; t < 6; t++) xv[t] = xs[ci][kh][tx * 4 + t];
                #pragma unroll
                for (int kw = 0; kw < 3; kw++) {
                    float4 wv = *(const float4*)&ws[ci][kh * 3 + kw][ty * 4];
                    float wr[4] = {wv.x, wv.y, wv.z, wv.w};
                    #pragma unroll
                    for (int i = 0; i < 4; i++)
                        #pragma unroll
                        for (int j = 0; j < 4; j++)
                            acc[i][j] = fmaf(wr[i], xv[kw + j], acc[i][j]);
                }
            }
        }
        __syncthreads();
    }
    #pragma unroll
    for (int i = 0; i < 4; i++) {
        long off = ((long)b * 256 + o0 + ty * 4 + i) * 4096 + h * 64 + tx * 4;
        *(float4*)(y + off) = make_float4(acc[i][0], acc[i][1], acc[i][2], acc[i][3]);
    }
}

// ---------------- BN (train-mode batch stats) + ReLU ----------------
__global__ void bnstats(const float* __restrict__ y, float* __restrict__ meanp,
                        float* __restrict__ rstdp) {
    __shared__ float sh[16];
    int o = blockIdx.x, tid = threadIdx.x;
    float s = 0.f, sq = 0.f;
    for (int b = 0; b < 4; b++) {
        const float4* p = (const float4*)(y + ((size_t)b * 256 + o) * 4096);
        for (int i = tid; i < 1024; i += 256) {
            float4 v = p[i];
            s += v.x + v.y + v.z + v.w;
            sq += v.x * v.x + v.y * v.y + v.z * v.z + v.w * v.w;
        }
    }
    s = warpSum(s); sq = warpSum(sq);
    if ((tid & 31) == 0) { sh[tid >> 5] = s; sh[8 + (tid >> 5)] = sq; }
    __syncthreads();
    if (tid == 0) {
        float S = 0.f, SQ = 0.f;
        for (int i = 0; i < 8; i++) { S += sh[i]; SQ += sh[8 + i]; }
        float mean = S / 16384.f;
        float var = SQ / 16384.f - mean * mean;
        meanp[o] = mean;
        rstdp[o] = rsqrtf(var + 1e-5f);
    }
}

__global__ void bnapply(const float* __restrict__ y, const float* __restrict__ gam,
                        const float* __restrict__ bet, const float* __restrict__ meanp,
                        const float* __restrict__ rstdp, float* __restrict__ out) {
    size_t i = (size_t)blockIdx.x * 256 + threadIdx.x;  // float4 index
    int o = (int)((i >> 10) & 255);
    float mu = meanp[o], rs = rstdp[o], g = gam[o], be = bet[o];
    float4 v = ((const float4*)y)[i];
    float4 r;
    r.x = fmaxf(0.f, fmaf((v.x - mu) * rs, g, be));
    r.y = fmaxf(0.f, fmaf((v.y - mu) * rs, g, be));
    r.z = fmaxf(0.f, fmaf((v.z - mu) * rs, g, be));
    r.w = fmaxf(0.f, fmaf((v.w - mu) * rs, g, be));
    ((float4*)out)[i] = r;
}

// ---------------- launcher ----------------
extern "C" void kernel_launch(void* const* d_in, const int* in_sizes, int n_in,
                              void* d_out, int out_size) {
    const float* x   = (const float*)d_in[0];
    const float* wq  = (const float*)d_in[1];
    const float* bq  = (const float*)d_in[2];
    const float* wk  = (const float*)d_in[3];
    const float* bk  = (const float*)d_in[4];
    const float* wv  = (const float*)d_in[5];
    const float* bv  = (const float*)d_in[6];
    const float* gpa = (const float*)d_in[7];
    const float* gca = (const float*)d_in[8];
    const float* wf  = (const float*)d_in[9];
    const float* bng = (const float*)d_in[10];
    const float* bnb = (const float*)d_in[11];
    float* out = (float*)d_out;

    float *q, *k, *v, *attn, *cat, *cattn, *y, *mean, *rstd;
    cudaGetSymbolAddress((void**)&q, g_q);
    cudaGetSymbolAddress((void**)&k, g_k);
    cudaGetSymbolAddress((void**)&v, g_v);
    cudaGetSymbolAddress((void**)&attn, g_attn);
    cudaGetSymbolAddress((void**)&cat, g_cat);
    cudaGetSymbolAddress((void**)&cattn, g_cattn);
    cudaGetSymbolAddress((void**)&y, g_y);
    cudaGetSymbolAddress((void**)&mean, g_mean);
    cudaGetSymbolAddress((void**)&rstd, g_rstd);

    dim3 blk(256);
    long sx = (long)C_ * N_;           // 1,048,576
    long sqk = (long)CQ_ * N_;
    long sattn = (long)N_ * N_;
    long scat = (long)2 * C_ * N_;

    // q, k, v projections (1x1 convs as GEMMs)
    gemm_nn_k<<<dim3(64, 1, 4), blk>>>(wq, x, q, CQ_, N_, C_, 0, bq, nullptr, nullptr,
                                       0, sx, sqk, 0);
    gemm_nn_k<<<dim3(64, 1, 4), blk>>>(wk, x, k, CQ_, N_, C_, 0, bk, nullptr, nullptr,
                                       0, sx, sqk, 0);
    gemm_nn_k<<<dim3(64, 4, 4), blk>>>(wv, x, v, C_, N_, C_, 0, bv, nullptr, nullptr,
                                       0, sx, sx, 0);
    // logits[i][j] = sum_d q[d][i] k[d][j]
    gemm_tn_k<<<dim3(64, 64, 4), blk>>>(q, k, attn, N_, N_, CQ_, 2, nullptr, nullptr,
                                        nullptr, sqk, sqk, sattn, 0);
    softmax4096<<<B_ * N_, 256>>>(attn);
    // pa[c][i] = gamma_pa * sum_j v[c][j] attn[i][j] + x[c][i]  -> cat[:, 0:256]
    gemm_nt_k<<<dim3(64, 4, 4), blk>>>(v, attn, cat, C_, N_, N_, 1, nullptr, gpa, x,
                                       sx, sattn, scat, sx);
    // channel logits[i][j] = sum_n x[i][n] x[j][n]
    gemm_nt_k<<<dim3(4, 4, 4), blk>>>(x, x, cattn, C_, C_, N_, 2, nullptr, nullptr,
                                      nullptr, sx, sx, (long)C_ * C_, 0);
    softmax256<<<B_ * C_, 256>>>(cattn);
    // ca[i][n] = gamma_ca * sum_j cattn[i][j] x[j][n] + x[i][n]  -> cat[:, 256:512]
    gemm_nn_k<<<dim3(64, 4, 4), blk>>>(cattn, x, cat + (size_t)C_ * N_, C_, N_, C_, 1,
                                       nullptr, gca, x, (long)C_ * C_, sx, scat, sx);
    // 3x3 conv 512->256
    conv3x3<<<dim3(4, 64, 4), blk>>>(cat, wf, y);
    // BN train-mode + ReLU
    bnstats<<<256, 256>>>(y, mean, rstd);
    bnapply<<<4096, 256>>>(y, bng, bnb, mean, rstd, out);
}

// round 3
// speedup vs baseline: 1.0024x; 1.0007x over previous
#include <cuda_runtime.h>

#define B_  4
#define C_  256
#define CQ_ 32
#define N_  4096
#define HW_ 64

// ---------------- scratch (device globals; no allocation) ----------------
__device__ float g_q[B_ * CQ_ * N_];
__device__ float g_k[B_ * CQ_ * N_];
__device__ float g_v[B_ * C_ * N_];
__device__ float g_attn[(size_t)B_ * N_ * N_];      // 256 MB
__device__ float g_cat[(size_t)B_ * 2 * C_ * N_];   // [b][512][4096]
__device__ float g_cattn[B_ * C_ * C_];
__device__ float g_y[(size_t)B_ * C_ * N_];
__device__ float g_mean[C_];
__device__ float g_rstd[C_];

// ---------------- helpers ----------------
__device__ __forceinline__ float warpMax(float v) {
    #pragma unroll
    for (int o = 16; o; o >>= 1) v = fmaxf(v, __shfl_xor_sync(0xffffffffu, v, o));
    return v;
}
__device__ __forceinline__ float warpSum(float v) {
    #pragma unroll
    for (int o = 16; o; o >>= 1) v += __shfl_xor_sync(0xffffffffu, v, o);
    return v;
}

// 64x64 tile compute: acc[4][4] += As[k][m] * Bs[k][n]
__device__ __forceinline__ void mma_tile(const float (*As)[64], const float (*Bs)[64],
                                         float acc[4][4], int ty, int tx) {
    #pragma unroll
    for (int k = 0; k < 16; k++) {
        float4 a = *(const float4*)&As[k][ty * 4];
        float4 b = *(const float4*)&Bs[k][tx * 4];
        float ar[4] = {a.x, a.y, a.z, a.w};
        float br[4] = {b.x, b.y, b.z, b.w};
        #pragma unroll
        for (int i = 0; i < 4; i++)
            #pragma unroll
            for (int j = 0; j < 4; j++)
                acc[i][j] = fmaf(ar[i], br[j], acc[i][j]);
    }
}

// epi: 0 -> +bias[m]; 1 -> gamma*acc + res[m*N+n]; 2 -> raw
__device__ __forceinline__ void epilogue(float* Out, int M, int N, int m0, int n0,
                                         int ty, int tx, float acc[4][4], int epi,
                                         const float* bias, const float* gsc,
                                         const float* res) {
    float g = gsc ? *gsc : 0.f;
    #pragma unroll
    for (int i = 0; i < 4; i++) {
        int m = m0 + ty * 4 + i;
        if (m < M) {
            long off = (long)m * N + n0 + tx * 4;
            float4 o;
            if (epi == 0) {
                float bv = bias[m];
                o = make_float4(acc[i][0] + bv, acc[i][1] + bv, acc[i][2] + bv, acc[i][3] + bv);
            } else if (epi == 1) {
                float4 r = *(const float4*)(res + off);
                o = make_float4(fmaf(g, acc[i][0], r.x), fmaf(g, acc[i][1], r.y),
                                fmaf(g, acc[i][2], r.z), fmaf(g, acc[i][3], r.w));
            } else {
                o = make_float4(acc[i][0], acc[i][1], acc[i][2], acc[i][3]);
            }
            *(float4*)(Out + off) = o;
        }
    }
}

// ---------------- GEMM kernels (BM=BN=64, BK=16, 256 threads, 4x4 microtile) ----------------

// Out[m][n] = sum_k A[m][k] * B[k][n]   (A: MxK row-major; B: KxN, n contiguous)
__global__ void gemm_nn_k(const float* __restrict__ A, const float* __restrict__ Bm,
                          float* __restrict__ Out, int M, int N, int K, int epi,
                          const float* __restrict__ bias, const float* __restrict__ gsc,
                          const float* __restrict__ res,
                          long sA, long sB, long sO, long sR) {
    int b = blockIdx.z;
    A += sA * b; Bm += sB * b; Out += sO * b;
    const float* resb = res ? res + sR * b : nullptr;
    __shared__ float As[16][64];
    __shared__ float Bs[16][64];
    int tid = threadIdx.x;
    int tx = tid & 15, ty = tid >> 4;
    int m0 = blockIdx.y * 64, n0 = blockIdx.x * 64;
    int arow = tid >> 2, ak = (tid & 3) * 4;
    int brow = tid >> 4, bn = (tid & 15) * 4;
    float acc[4][4] = {};
    for (int k0 = 0; k0 < K; k0 += 16) {
        float4 av = make_float4(0.f, 0.f, 0.f, 0.f);
        if (m0 + arow < M) av = *(const float4*)(A + (long)(m0 + arow) * K + k0 + ak);
        As[ak + 0][arow] = av.x; As[ak + 1][arow] = av.y;
        As[ak + 2][arow] = av.z; As[ak + 3][arow] = av.w;
        *(float4*)&Bs[brow][bn] = *(const float4*)(Bm + (long)(k0 + brow) * N + n0 + bn);
        __syncthreads();
        mma_tile(As, Bs, acc, ty, tx);
        __syncthreads();
    }
    epilogue(Out, M, N, m0, n0, ty, tx, acc, epi, bias, gsc, resb);
}

// Out[m][n] = sum_k A[m][k] * B[n][k]   (both K-contiguous)
__global__ void gemm_nt_k(const float* __restrict__ A, const float* __restrict__ Bm,
                          float* __restrict__ Out, int M, int N, int K, int epi,
                          const float* __restrict__ bias, const float* __restrict__ gsc,
                          const float* __restrict__ res,
                          long sA, long sB, long sO, long sR) {
    int b = blockIdx.z;
    A += sA * b; Bm += sB * b; Out += sO * b;
    const float* resb = res ? res + sR * b : nullptr;
    __shared__ float As[16][64];
    __shared__ float Bs[16][64];
    int tid = threadIdx.x;
    int tx = tid & 15, ty = tid >> 4;
    int m0 = blockIdx.y * 64, n0 = blockIdx.x * 64;
    int arow = tid >> 2, ak = (tid & 3) * 4;
    float acc[4][4] = {};
    for (int k0 = 0; k0 < K; k0 += 16) {
        float4 av = make_float4(0.f, 0.f, 0.f, 0.f);
        if (m0 + arow < M) av = *(const float4*)(A + (long)(m0 + arow) * K + k0 + ak);
        As[ak + 0][arow] = av.x; As[ak + 1][arow] = av.y;
        As[ak + 2][arow] = av.z; As[ak + 3][arow] = av.w;
        float4 bv = *(const float4*)(Bm + (long)(n0 + arow) * K + k0 + ak);
        Bs[ak + 0][arow] = bv.x; Bs[ak + 1][arow] = bv.y;
        Bs[ak + 2][arow] = bv.z; Bs[ak + 3][arow] = bv.w;
        __syncthreads();
        mma_tile(As, Bs, acc, ty, tx);
        __syncthreads();
    }
    epilogue(Out, M, N, m0, n0, ty, tx, acc, epi, bias, gsc, resb);
}

// Out[m][n] = sum_k A[k][m] * B[k][n]   (A: KxM m-contig; B: KxN n-contig)
__global__ void gemm_tn_k(const float* __restrict__ A, const float* __restrict__ Bm,
                          float* __restrict__ Out, int M, int N, int K, int epi,
                          const float* __restrict__ bias, const float* __restrict__ gsc,
                          const float* __restrict__ res,
                          long sA, long sB, long sO, long sR) {
    int b = blockIdx.z;
    A += sA * b; Bm += sB * b; Out += sO * b;
    const float* resb = res ? res + sR * b : nullptr;
    __shared__ float As[16][64];
    __shared__ float Bs[16][64];
    int tid = threadIdx.x;
    int tx = tid & 15, ty = tid >> 4;
    int m0 = blockIdx.y * 64, n0 = blockIdx.x * 64;
    int krow = tid >> 4, c4 = (tid & 15) * 4;
    float acc[4][4] = {};
    for (int k0 = 0; k0 < K; k0 += 16) {
        *(float4*)&As[krow][c4] = *(const float4*)(A + (long)(k0 + krow) * M + m0 + c4);
        *(float4*)&Bs[krow][c4] = *(const float4*)(Bm + (long)(k0 + krow) * N + n0 + c4);
        __syncthreads();
        mma_tile(As, Bs, acc, ty, tx);
        __syncthreads();
    }
    epilogue(Out, M, N, m0, n0, ty, tx, acc, epi, bias, gsc, resb);
}

// ---------------- softmax ----------------
__global__ void softmax4096(float* __restrict__ data) {
    __shared__ float sh[8];
    float4* p = (float4*)(data + (size_t)blockIdx.x * 4096);
    int tid = threadIdx.x;
    float4 v[4];
    #pragma unroll
    for (int j = 0; j < 4; j++) v[j] = p[tid + 256 * j];
    float m = -3e38f;
    #pragma unroll
    for (int j = 0; j < 4; j++) {
        m = fmaxf(m, fmaxf(fmaxf(v[j].x, v[j].y), fmaxf(v[j].z, v[j].w)));
    }
    m = warpMax(m);
    if ((tid & 31) == 0) sh[tid >> 5] = m;
    __syncthreads();
    m = sh[tid & 7];
    #pragma unroll
    for (int o = 4; o; o >>= 1) m = fmaxf(m, __shfl_xor_sync(0xffffffffu, m, o));
    __syncthreads();
    float s = 0.f;
    #pragma unroll
    for (int j = 0; j < 4; j++) {
        v[j].x = __expf(v[j].x - m); v[j].y = __expf(v[j].y - m);
        v[j].z = __expf(v[j].z - m); v[j].w = __expf(v[j].w - m);
        s += v[j].x + v[j].y + v[j].z + v[j].w;
    }
    s = warpSum(s);
    if ((tid & 31) == 0) sh[tid >> 5] = s;
    __syncthreads();
    s = sh[tid & 7];
    #pragma unroll
    for (int o = 4; o; o >>= 1) s += __shfl_xor_sync(0xffffffffu, s, o);
    float inv = 1.f / s;
    #pragma unroll
    for (int j = 0; j < 4; j++) {
        v[j].x *= inv; v[j].y *= inv; v[j].z *= inv; v[j].w *= inv;
        p[tid + 256 * j] = v[j];
    }
}

__global__ void softmax256(float* __restrict__ data) {
    __shared__ float sh[8];
    float* p = data + (size_t)blockIdx.x * 256;
    int tid = threadIdx.x;
    float v = p[tid];
    float m = warpMax(v);
    if ((tid & 31) == 0) sh[tid >> 5] = m;
    __syncthreads();
    m = sh[tid & 7];
    #pragma unroll
    for (int o = 4; o; o >>= 1) m = fmaxf(m, __shfl_xor_sync(0xffffffffu, m, o));
    __syncthreads();
    float e = __expf(v - m);
    float s = warpSum(e);
    if ((tid & 31) == 0) sh[tid >> 5] = s;
    __syncthreads();
    s = sh[tid & 7];
    #pragma unroll
    for (int o = 4; o; o >>= 1) s += __shfl_xor_sync(0xffffffffu, s, o);
    p[tid] = e / s;
}

// ---------------- 3x3 conv, 512 -> 256, pad 1 ----------------
// grid: (4 o-tiles, 64 h, 4 b); block 256. Each block: y[b, o0:o0+64, h, 0:64]
__global__ void conv3x3(const float* __restrict__ cat, const float* __restrict__ wf,
                        float* __restrict__ y) {
    __shared__ float xs[8][3][66];
    __shared__ float ws[8][9][64];
    int b = blockIdx.z, h = blockIdx.y, o0 = blockIdx.x * 64;
    int tid = threadIdx.x;
    int tx = tid & 15, ty = tid >> 4;   // w-micro = tx*4, o-micro = ty*4
    float acc[4][4] = {};               // [o][w]
    for (int c0 = 0; c0 < 512; c0 += 8) {
        // input patch: 8 ci x 3 rows x 64 w (with zero halo in w)
        for (int idx = tid; idx < 8 * 3 * 64; idx += 256) {
            int ci = idx / 192;
            int r = (idx / 64) % 3;
            int w = idx % 64;
            int hh = h + r - 1;
            float val = 0.f;
            if (hh >= 0 && hh < 64)
                val = cat[((long)b * 512 + c0 + ci) * 4096 + hh * 64 + w];
            xs[ci][r][w + 1] = val;
        }
        if (tid < 24) {
            int ci = tid / 3, r = tid % 3;
            xs[ci][r][0] = 0.f; xs[ci][r][65] = 0.f;
        }
        // weights: ws[ci][khkw][o]
        for (int idx = tid; idx < 8 * 9 * 64; idx += 256) {
            int o = idx / 72;
            int r = idx % 72;
            int ci = r / 9, kk = r % 9;
            ws[ci][kk][o] = wf[(long)(o0 + o) * 4608 + (c0 + ci) * 9 + kk];
        }
        __syncthreads();
        #pragma unroll
        for (int ci = 0; ci < 8; ci++) {
            #pragma unroll
            for (int kh = 0; kh < 3; kh++) {
                float xv[6];
                #pragma unroll
                for (int t = 0; t < 6; t++) xv[t] = xs[ci][kh][tx * 4 + t];
                #pragma unroll
                for (int kw = 0; kw < 3; kw++) {
                    float4 wv = *(const float4*)&ws[ci][kh * 3 + kw][ty * 4];
                    float wr[4] = {wv.x, wv.y, wv.z, wv.w};
                    #pragma unroll
                    for (int i = 0; i < 4; i++)
                        #pragma unroll
                        for (int j = 0; j < 4; j++)
                            acc[i][j] = fmaf(wr[i], xv[kw + j], acc[i][j]);
                }
            }
        }
        __syncthreads();
    }
    #pragma unroll
    for (int i = 0; i < 4; i++) {
        long off = ((long)b * 256 + o0 + ty * 4 + i) * 4096 + h * 64 + tx * 4;
        *(float4*)(y + off) = make_float4(acc[i][0], acc[i][1], acc[i][2], acc[i][3]);
    }
}

// ---------------- BN (train-mode batch stats) + ReLU ----------------
__global__ void bnstats(const float* __restrict__ y, float* __restrict__ meanp,
                        float* __restrict__ rstdp) {
    __shared__ float sh[16];
    int o = blockIdx.x, tid = threadIdx.x;
    float s = 0.f, sq = 0.f;
    for (int b = 0; b < 4; b++) {
        const float4* p = (const float4*)(y + ((size_t)b * 256 + o) * 4096);
        for (int i = tid; i < 1024; i += 256) {
            float4 v = p[i];
            s += v.x + v.y + v.z + v.w;
            sq += v.x * v.x + v.y * v.y + v.z * v.z + v.w * v.w;
        }
    }
    s = warpSum(s); sq = warpSum(sq);
    if ((tid & 31) == 0) { sh[tid >> 5] = s; sh[8 + (tid >> 5)] = sq; }
    __syncthreads();
    if (tid == 0) {
        float S = 0.f, SQ = 0.f;
        for (int i = 0; i < 8; i++) { S += sh[i]; SQ += sh[8 + i]; }
        float mean = S / 16384.f;
        float var = SQ / 16384.f - mean * mean;
        meanp[o] = mean;
        rstdp[o] = rsqrtf(var + 1e-5f);
    }
}

__global__ void bnapply(const float* __restrict__ y, const float* __restrict__ gam,
                        const float* __restrict__ bet, const float* __restrict__ meanp,
                        const float* __restrict__ rstdp, float* __restrict__ out) {
    size_t i = (size_t)blockIdx.x * 256 + threadIdx.x;  // float4 index
    int o = (int)((i >> 10) & 255);
    float mu = meanp[o], rs = rstdp[o], g = gam[o], be = bet[o];
    float4 v = ((const float4*)y)[i];
    float4 r;
    r.x = fmaxf(0.f, fmaf((v.x - mu) * rs, g, be));
    r.y = fmaxf(0.f, fmaf((v.y - mu) * rs, g, be));
    r.z = fmaxf(0.f, fmaf((v.z - mu) * rs, g, be));
    r.w = fmaxf(0.f, fmaf((v.w - mu) * rs, g, be));
    ((float4*)out)[i] = r;
}

// ---------------- launcher ----------------
extern "C" void kernel_launch(void* const* d_in, const int* in_sizes, int n_in,
                              void* d_out, int out_size) {
    const float* x   = (const float*)d_in[0];
    const float* wq  = (const float*)d_in[1];
    const float* bq  = (const float*)d_in[2];
    const float* wk  = (const float*)d_in[3];
    const float* bk  = (const float*)d_in[4];
    const float* wv  = (const float*)d_in[5];
    const float* bv  = (const float*)d_in[6];
    const float* gpa = (const float*)d_in[7];
    const float* gca = (const float*)d_in[8];
    const float* wf  = (const float*)d_in[9];
    const float* bng = (const float*)d_in[10];
    const float* bnb = (const float*)d_in[11];
    float* out = (float*)d_out;

    float *q, *k, *v, *attn, *cat, *cattn, *y, *mean, *rstd;
    cudaGetSymbolAddress((void**)&q, g_q);
    cudaGetSymbolAddress((void**)&k, g_k);
    cudaGetSymbolAddress((void**)&v, g_v);
    cudaGetSymbolAddress((void**)&attn, g_attn);
    cudaGetSymbolAddress((void**)&cat, g_cat);
    cudaGetSymbolAddress((void**)&cattn, g_cattn);
    cudaGetSymbolAddress((void**)&y, g_y);
    cudaGetSymbolAddress((void**)&mean, g_mean);
    cudaGetSymbolAddress((void**)&rstd, g_rstd);

    dim3 blk(256);
    long sx = (long)C_ * N_;           // 1,048,576
    long sqk = (long)CQ_ * N_;
    long sattn = (long)N_ * N_;
    long scat = (long)2 * C_ * N_;

    // q, k, v projections (1x1 convs as GEMMs)
    gemm_nn_k<<<dim3(64, 1, 4), blk>>>(wq, x, q, CQ_, N_, C_, 0, bq, nullptr, nullptr,
                                       0, sx, sqk, 0);
    gemm_nn_k<<<dim3(64, 1, 4), blk>>>(wk, x, k, CQ_, N_, C_, 0, bk, nullptr, nullptr,
                                       0, sx, sqk, 0);
    gemm_nn_k<<<dim3(64, 4, 4), blk>>>(wv, x, v, C_, N_, C_, 0, bv, nullptr, nullptr,
                                       0, sx, sx, 0);
    // logits[i][j] = sum_d q[d][i] k[d][j]
    gemm_tn_k<<<dim3(64, 64, 4), blk>>>(q, k, attn, N_, N_, CQ_, 2, nullptr, nullptr,
                                        nullptr, sqk, sqk, sattn, 0);
    softmax4096<<<B_ * N_, 256>>>(attn);
    // pa[c][i] = gamma_pa * sum_j v[c][j] attn[i][j] + x[c][i]  -> cat[:, 0:256]
    gemm_nt_k<<<dim3(64, 4, 4), blk>>>(v, attn, cat, C_, N_, N_, 1, nullptr, gpa, x,
                                       sx, sattn, scat, sx);
    // channel logits[i][j] = sum_n x[i][n] x[j][n]
    gemm_nt_k<<<dim3(4, 4, 4), blk>>>(x, x, cattn, C_, C_, N_, 2, nullptr, nullptr,
                                      nullptr, sx, sx, (long)C_ * C_, 0);
    softmax256<<<B_ * C_, 256>>>(cattn);
    // ca[i][n] = gamma_ca * sum_j cattn[i][j] x[j][n] + x[i][n]  -> cat[:, 256:512]
    gemm_nn_k<<<dim3(64, 4, 4), blk>>>(cattn, x, cat + (size_t)C_ * N_, C_, N_, C_, 1,
                                       nullptr, gca, x, (long)C_ * C_, sx, scat, sx);
    // 3x3 conv 512->256
    conv3x3<<<dim3(4, 64, 4), blk>>>(cat, wf, y);
    // BN train-mode + ReLU
    bnstats<<<256, 256>>>(y, mean, rstd);
    bnapply<<<4096, 256>>>(y, bng, bnb, mean, rstd, out);
}

// round 5
// speedup vs baseline: 2.4846x; 2.4786x over previous
#include <cuda_runtime.h>
#include <cstdint>

#define B_  4
#define C_  256
#define CQ_ 32
#define N_  4096
#define HW_ 64

// ---------------- scratch (device globals; no allocation) ----------------
__device__ float g_q[B_ * CQ_ * N_];
__device__ float g_k[B_ * CQ_ * N_];
__device__ float g_v[B_ * C_ * N_];
__device__ float g_attn[(size_t)B_ * N_ * N_];      // 256 MB
__device__ float g_cat[(size_t)B_ * 2 * C_ * N_];   // [b][512][4096]
__device__ float g_cattn[B_ * C_ * C_];
__device__ float g_y[(size_t)B_ * C_ * N_];
__device__ float g_mean[C_];
__device__ float g_rstd[C_];

// ---------------- PTX helpers (sm_80+ mma.sync / cp.async) ----------------
__device__ __forceinline__ uint32_t smem_to_u32(const void* p) {
    uint32_t a;
    asm("{ .reg .u64 t; cvta.to.shared.u64 t, %1; cvt.u32.u64 %0, t; }" : "=r"(a) : "l"(p));
    return a;
}
__device__ __forceinline__ void cp16(uint32_t dst, const void* src) {
    asm volatile("cp.async.cg.shared.global [%0], [%1], 16;" :: "r"(dst), "l"(src));
}
#define CP_COMMIT() asm volatile("cp.async.commit_group;" ::: "memory")
#define CP_WAIT(n)  asm volatile("cp.async.wait_group %0;" :: "n"(n) : "memory")

__device__ __forceinline__ uint32_t ld_tf32(const float* p) {
    uint32_t r;
    float f = *p;
    asm("cvt.rna.tf32.f32 %0, %1;" : "=r"(r) : "f"(f));
    return r;
}
__device__ __forceinline__ void mma_tf32(float c[4], uint32_t a0, uint32_t a1,
                                         uint32_t a2, uint32_t a3,
                                         uint32_t b0, uint32_t b1) {
    asm volatile(
        "mma.sync.aligned.m16n8k8.row.col.f32.tf32.tf32.f32 "
        "{%0,%1,%2,%3}, {%4,%5,%6,%7}, {%8,%9}, {%0,%1,%2,%3};"
        : "+f"(c[0]), "+f"(c[1]), "+f"(c[2]), "+f"(c[3])
        : "r"(a0), "r"(a1), "r"(a2), "r"(a3), "r"(b0), "r"(b1));
}

// =================================================================
// PA GEMM (tf32 mma.sync):
//   cat[b, c, i] = gamma_pa * sum_j v[b,c,j] * attn[b,i,j] + x[b,c,i]
// CTA tile 128(m=c) x 128(n=i), K=4096, BK=32, cp.async double buffer.
// 8 warps as 4(m) x 2(n); warp tile 32x64; mma m16n8k8.
// smem: As[2][128][36] + Bs[2][128][36]  (pad 36 -> conflict-free frags)
// =================================================================
#define PA_SMEM_BYTES (4 * 128 * 36 * 4)   // 73728

__global__ void __launch_bounds__(256)
pa_mma(const float* __restrict__ v, const float* __restrict__ attn,
       const float* __restrict__ x, const float* __restrict__ gpa,
       float* __restrict__ cat) {
    extern __shared__ float sm[];
    int tid = threadIdx.x, lane = tid & 31, wid = tid >> 5;
    int wm = wid & 3, wn = wid >> 2;
    int b = blockIdx.z, m0 = blockIdx.y * 128, n0 = blockIdx.x * 128;
    const float* Ag = v + (long)b * C_ * N_ + (long)m0 * N_;
    const float* Bg = attn + (long)b * N_ * N_ + (long)n0 * N_;
    uint32_t smu = smem_to_u32(sm);

    float c[2][8][4] = {};

    int flat_r[4], flat_q[4];
    #pragma unroll
    for (int j = 0; j < 4; j++) { int f = tid + 256 * j; flat_r[j] = f >> 3; flat_q[j] = (f & 7) * 4; }

    // prologue: load stages 0,1
    #pragma unroll
    for (int s = 0; s < 2; s++) {
        int k0 = s * 32;
        #pragma unroll
        for (int j = 0; j < 4; j++) {
            int r = flat_r[j], q = flat_q[j];
            cp16(smu + (s * 4608 + r * 36 + q) * 4, Ag + (long)r * N_ + k0 + q);
            cp16(smu + (9216 + s * 4608 + r * 36 + q) * 4, Bg + (long)r * N_ + k0 + q);
        }
        CP_COMMIT();
    }

    for (int ch = 0; ch < 128; ch++) {
        if (ch < 126) { CP_WAIT(1); } else { CP_WAIT(0); }
        __syncthreads();
        const float* As_ = sm + (ch & 1) * 4608;
        const float* Bs_ = sm + 9216 + (ch & 1) * 4608;
        #pragma unroll
        for (int k8 = 0; k8 < 32; k8 += 8) {
            uint32_t a[2][4], bb[8][2];
            #pragma unroll
            for (int mt = 0; mt < 2; mt++) {
                const float* ap = As_ + (wm * 32 + mt * 16 + (lane >> 2)) * 36 + k8 + (lane & 3);
                a[mt][0] = ld_tf32(ap);
                a[mt][1] = ld_tf32(ap + 8 * 36);
                a[mt][2] = ld_tf32(ap + 4);
                a[mt][3] = ld_tf32(ap + 8 * 36 + 4);
            }
            #pragma unroll
            for (int nt = 0; nt < 8; nt++) {
                const float* bp = Bs_ + (wn * 64 + nt * 8 + (lane >> 2)) * 36 + k8 + (lane & 3);
                bb[nt][0] = ld_tf32(bp);
                bb[nt][1] = ld_tf32(bp + 4);
            }
            #pragma unroll
            for (int mt = 0; mt < 2; mt++)
                #pragma unroll
                for (int nt = 0; nt < 8; nt++)
                    mma_tf32(c[mt][nt], a[mt][0], a[mt][1], a[mt][2], a[mt][3],
                             bb[nt][0], bb[nt][1]);
        }
        __syncthreads();
        if (ch + 2 < 128) {
            int s = ch & 1;
            int k0 = (ch + 2) * 32;
            #pragma unroll
            for (int j = 0; j < 4; j++) {
                int r = flat_r[j], q = flat_q[j];
                cp16(smu + (s * 4608 + r * 36 + q) * 4, Ag + (long)r * N_ + k0 + q);
                cp16(smu + (9216 + s * 4608 + r * 36 + q) * 4, Bg + (long)r * N_ + k0 + q);
            }
            CP_COMMIT();
        }
    }

    // epilogue: gamma*acc + x -> cat channels [0,256)
    float g = gpa[0];
    #pragma unroll
    for (int mt = 0; mt < 2; mt++) {
        #pragma unroll
        for (int nt = 0; nt < 8; nt++) {
            int row = m0 + wm * 32 + mt * 16 + (lane >> 2);
            int col = n0 + wn * 64 + nt * 8 + 2 * (lane & 3);
            long xo = ((long)b * C_ + row) * N_ + col;
            long co = ((long)b * 2 * C_ + row) * N_ + col;
            float2 x0 = *(const float2*)(x + xo);
            *(float2*)(cat + co) =
                make_float2(fmaf(g, c[mt][nt][0], x0.x), fmaf(g, c[mt][nt][1], x0.y));
            float2 x1 = *(const float2*)(x + xo + 8 * N_);
            *(float2*)(cat + co + 8 * N_) =
                make_float2(fmaf(g, c[mt][nt][2], x1.x), fmaf(g, c[mt][nt][3], x1.y));
        }
    }
}

// =================================================================
// 3x3 conv 512->256 as implicit GEMM (tf32 mma.sync):
//   y[b,o,p] = sum_{ci,kh,kw} wf[o][ci][kh][kw] * cat[b,ci, p shifted]
// CTA: 128(o) x 128(p = 2 h-rows). K = 512*9 in ci-chunks of 8 (K=72).
// smem: As[128][76] weights, Bs[128][76] im2col, patch[8][4][66].
// =================================================================
#define CV_SMEM_BYTES ((9728 + 9728 + 2112) * 4)   // 86272

__global__ void __launch_bounds__(256)
conv_mma(const float* __restrict__ cat, const float* __restrict__ wf,
         float* __restrict__ y) {
    extern __shared__ float sm[];
    float* As = sm;             // 128*76
    float* Bs = sm + 9728;      // 128*76
    float* patch = sm + 19456;  // 8*4*66
    int tid = threadIdx.x, lane = tid & 31, wid = tid >> 5;
    int wm = wid & 3, wn = wid >> 2;
    int b = blockIdx.z, o0 = blockIdx.y * 128, p0 = blockIdx.x * 128;
    int h0 = blockIdx.x * 2;
    uint32_t smu = smem_to_u32(sm);

    float c[2][8][4] = {};

    for (int chunk = 0; chunk < 64; chunk++) {
        __syncthreads();     // previous compute done; safe to overwrite
        // weights A: 128 rows x 72 k  (wf row-major [o][4608], k contiguous)
        #pragma unroll
        for (int j = 0; j < 9; j++) {
            int flat = tid + 256 * j;
            int r = flat / 18, q = (flat % 18) * 4;
            cp16(smu + (r * 76 + q) * 4, wf + (long)(o0 + r) * 4608 + chunk * 72 + q);
        }
        CP_COMMIT();
        // input patch 8ci x 4 rows x 66 (zero halo)
        int ci0 = chunk * 8;
        #pragma unroll
        for (int p = 0; p < 8; p++) {
            int flat = p * 256 + tid;
            int ci = flat >> 8, row = (flat >> 6) & 3, w = flat & 63;
            int h = h0 - 1 + row;
            float val = (h >= 0 && h < 64)
                ? cat[((long)b * 512 + ci0 + ci) * 4096 + h * 64 + w] : 0.f;
            patch[ci * 264 + row * 66 + w + 1] = val;
        }
        if (tid < 64) {
            int ci = tid >> 3, row = (tid >> 1) & 3, side = tid & 1;
            patch[ci * 264 + row * 66 + side * 65] = 0.f;
        }
        CP_WAIT(0);
        __syncthreads();
        // build im2col Bs[n][k], k = (ci_l + half*4)*9 + kh*3 + kw
        {
            int n = tid >> 1, half = tid & 1;
            int hh = n >> 6, w = n & 63;
            const float* pb = patch + half * 4 * 264 + hh * 66 + w;
            float* brow = Bs + n * 76 + half * 36;
            #pragma unroll
            for (int ci_l = 0; ci_l < 4; ci_l++)
                #pragma unroll
                for (int kh = 0; kh < 3; kh++)
                    #pragma unroll
                    for (int kw = 0; kw < 3; kw++)
                        brow[ci_l * 9 + kh * 3 + kw] = pb[ci_l * 264 + kh * 66 + kw];
        }
        __syncthreads();
        // 9 k8-steps over K=72
        #pragma unroll
        for (int k8 = 0; k8 < 72; k8 += 8) {
            uint32_t a[2][4], bb[8][2];
            #pragma unroll
            for (int mt = 0; mt < 2; mt++) {
                const float* ap = As + (wm * 32 + mt * 16 + (lane >> 2)) * 76 + k8 + (lane & 3);
                a[mt][0] = ld_tf32(ap);
                a[mt][1] = ld_tf32(ap + 8 * 76);
                a[mt][2] = ld_tf32(ap + 4);
                a[mt][3] = ld_tf32(ap + 8 * 76 + 4);
            }
            #pragma unroll
            for (int nt = 0; nt < 8; nt++) {
                const float* bp = Bs + (wn * 64 + nt * 8 + (lane >> 2)) * 76 + k8 + (lane & 3);
                bb[nt][0] = ld_tf32(bp);
                bb[nt][1] = ld_tf32(bp + 4);
            }
            #pragma unroll
            for (int mt = 0; mt < 2; mt++)
                #pragma unroll
                for (int nt = 0; nt < 8; nt++)
                    mma_tf32(c[mt][nt], a[mt][0], a[mt][1], a[mt][2], a[mt][3],
                             bb[nt][0], bb[nt][1]);
        }
    }

    // epilogue: raw conv output to y
    #pragma unroll
    for (int mt = 0; mt < 2; mt++) {
        #pragma unroll
        for (int nt = 0; nt < 8; nt++) {
            int row = o0 + wm * 32 + mt * 16 + (lane >> 2);
            int col = p0 + wn * 64 + nt * 8 + 2 * (lane & 3);
            long yo = ((long)b * 256 + row) * 4096 + col;
            *(float2*)(y + yo) = make_float2(c[mt][nt][0], c[mt][nt][1]);
            *(float2*)(y + yo + 8 * 4096) = make_float2(c[mt][nt][2], c[mt][nt][3]);
        }
    }
}

// ---------------- helpers ----------------
__device__ __forceinline__ float warpMax(float v) {
    #pragma unroll
    for (int o = 16; o; o >>= 1) v = fmaxf(v, __shfl_xor_sync(0xffffffffu, v, o));
    return v;
}
__device__ __forceinline__ float warpSum(float v) {
    #pragma unroll
    for (int o = 16; o; o >>= 1) v += __shfl_xor_sync(0xffffffffu, v, o);
    return v;
}

// 64x64 tile compute: acc[4][4] += As[k][m] * Bs[k][n]
__device__ __forceinline__ void mma_tile(const float (*As)[64], const float (*Bs)[64],
                                         float acc[4][4], int ty, int tx) {
    #pragma unroll
    for (int k = 0; k < 16; k++) {
        float4 a = *(const float4*)&As[k][ty * 4];
        float4 b = *(const float4*)&Bs[k][tx * 4];
        float ar[4] = {a.x, a.y, a.z, a.w};
        float br[4] = {b.x, b.y, b.z, b.w};
        #pragma unroll
        for (int i = 0; i < 4; i++)
            #pragma unroll
            for (int j = 0; j < 4; j++)
                acc[i][j] = fmaf(ar[i], br[j], acc[i][j]);
    }
}

// epi: 0 -> +bias[m]; 1 -> gamma*acc + res[m*N+n]; 2 -> raw
__device__ __forceinline__ void epilogue(float* Out, int M, int N, int m0, int n0,
                                         int ty, int tx, float acc[4][4], int epi,
                                         const float* bias, const float* gsc,
                                         const float* res) {
    float g = gsc ? *gsc : 0.f;
    #pragma unroll
    for (int i = 0; i < 4; i++) {
        int m = m0 + ty * 4 + i;
        if (m < M) {
            long off = (long)m * N + n0 + tx * 4;
            float4 o;
            if (epi == 0) {
                float bv = bias[m];
                o = make_float4(acc[i][0] + bv, acc[i][1] + bv, acc[i][2] + bv, acc[i][3] + bv);
            } else if (epi == 1) {
                float4 r = *(const float4*)(res + off);
                o = make_float4(fmaf(g, acc[i][0], r.x), fmaf(g, acc[i][1], r.y),
                                fmaf(g, acc[i][2], r.z), fmaf(g, acc[i][3], r.w));
            } else {
                o = make_float4(acc[i][0], acc[i][1], acc[i][2], acc[i][3]);
            }
            *(float4*)(Out + off) = o;
        }
    }
}

// ---------------- fp32 GEMM kernels (small ops) ----------------

__global__ void gemm_nn_k(const float* __restrict__ A, const float* __restrict__ Bm,
                          float* __restrict__ Out, int M, int N, int K, int epi,
                          const float* __restrict__ bias, const float* __restrict__ gsc,
                          const float* __restrict__ res,
                          long sA, long sB, long sO, long sR) {
    int b = blockIdx.z;
    A += sA * b; Bm += sB * b; Out += sO * b;
    const float* resb = res ? res + sR * b : nullptr;
    __shared__ float As[16][64];
    __shared__ float Bs[16][64];
    int tid = threadIdx.x;
    int tx = tid & 15, ty = tid >> 4;
    int m0 = blockIdx.y * 64, n0 = blockIdx.x * 64;
    int arow = tid >> 2, ak = (tid & 3) * 4;
    int brow = tid >> 4, bn = (tid & 15) * 4;
    float acc[4][4] = {};
    for (int k0 = 0; k0 < K; k0 += 16) {
        float4 av = make_float4(0.f, 0.f, 0.f, 0.f);
        if (m0 + arow < M) av = *(const float4*)(A + (long)(m0 + arow) * K + k0 + ak);
        As[ak + 0][arow] = av.x; As[ak + 1][arow] = av.y;
        As[ak + 2][arow] = av.z; As[ak + 3][arow] = av.w;
        *(float4*)&Bs[brow][bn] = *(const float4*)(Bm + (long)(k0 + brow) * N + n0 + bn);
        __syncthreads();
        mma_tile(As, Bs, acc, ty, tx);
        __syncthreads();
    }
    epilogue(Out, M, N, m0, n0, ty, tx, acc, epi, bias, gsc, resb);
}

__global__ void gemm_nt_k(const float* __restrict__ A, const float* __restrict__ Bm,
                          float* __restrict__ Out, int M, int N, int K, int epi,
                          const float* __restrict__ bias, const float* __restrict__ gsc,
                          const float* __restrict__ res,
                          long sA, long sB, long sO, long sR) {
    int b = blockIdx.z;
    A += sA * b; Bm += sB * b; Out += sO * b;
    const float* resb = res ? res + sR * b : nullptr;
    __shared__ float As[16][64];
    __shared__ float Bs[16][64];
    int tid = threadIdx.x;
    int tx = tid & 15, ty = tid >> 4;
    int m0 = blockIdx.y * 64, n0 = blockIdx.x * 64;
    int arow = tid >> 2, ak = (tid & 3) * 4;
    float acc[4][4] = {};
    for (int k0 = 0; k0 < K; k0 += 16) {
        float4 av = make_float4(0.f, 0.f, 0.f, 0.f);
        if (m0 + arow < M) av = *(const float4*)(A + (long)(m0 + arow) * K + k0 + ak);
        As[ak + 0][arow] = av.x; As[ak + 1][arow] = av.y;
        As[ak + 2][arow] = av.z; As[ak + 3][arow] = av.w;
        float4 bv = *(const float4*)(Bm + (long)(n0 + arow) * K + k0 + ak);
        Bs[ak + 0][arow] = bv.x; Bs[ak + 1][arow] = bv.y;
        Bs[ak + 2][arow] = bv.z; Bs[ak + 3][arow] = bv.w;
        __syncthreads();
        mma_tile(As, Bs, acc, ty, tx);
        __syncthreads();
    }
    epilogue(Out, M, N, m0, n0, ty, tx, acc, epi, bias, gsc, resb);
}

__global__ void gemm_tn_k(const float* __restrict__ A, const float* __restrict__ Bm,
                          float* __restrict__ Out, int M, int N, int K, int epi,
                          const float* __restrict__ bias, const float* __restrict__ gsc,
                          const float* __restrict__ res,
                          long sA, long sB, long sO, long sR) {
    int b = blockIdx.z;
    A += sA * b; Bm += sB * b; Out += sO * b;
    const float* resb = res ? res + sR * b : nullptr;
    __shared__ float As[16][64];
    __shared__ float Bs[16][64];
    int tid = threadIdx.x;
    int tx = tid & 15, ty = tid >> 4;
    int m0 = blockIdx.y * 64, n0 = blockIdx.x * 64;
    int krow = tid >> 4, c4 = (tid & 15) * 4;
    float acc[4][4] = {};
    for (int k0 = 0; k0 < K; k0 += 16) {
        *(float4*)&As[krow][c4] = *(const float4*)(A + (long)(k0 + krow) * M + m0 + c4);
        *(float4*)&Bs[krow][c4] = *(const float4*)(Bm + (long)(k0 + krow) * N + n0 + c4);
        __syncthreads();
        mma_tile(As, Bs, acc, ty, tx);
        __syncthreads();
    }
    epilogue(Out, M, N, m0, n0, ty, tx, acc, epi, bias, gsc, resb);
}

// ---------------- softmax ----------------
__global__ void softmax4096(float* __restrict__ data) {
    __shared__ float sh[8];
    float4* p = (float4*)(data + (size_t)blockIdx.x * 4096);
    int tid = threadIdx.x;
    float4 v[4];
    #pragma unroll
    for (int j = 0; j < 4; j++) v[j] = p[tid + 256 * j];
    float m = -3e38f;
    #pragma unroll
    for (int j = 0; j < 4; j++)
        m = fmaxf(m, fmaxf(fmaxf(v[j].x, v[j].y), fmaxf(v[j].z, v[j].w)));
    m = warpMax(m);
    if ((tid & 31) == 0) sh[tid >> 5] = m;
    __syncthreads();
    m = sh[tid & 7];
    #pragma unroll
    for (int o = 4; o; o >>= 1) m = fmaxf(m, __shfl_xor_sync(0xffffffffu, m, o));
    __syncthreads();
    float s = 0.f;
    #pragma unroll
    for (int j = 0; j < 4; j++) {
        v[j].x = __expf(v[j].x - m); v[j].y = __expf(v[j].y - m);
        v[j].z = __expf(v[j].z - m); v[j].w = __expf(v[j].w - m);
        s += v[j].x + v[j].y + v[j].z + v[j].w;
    }
    s = warpSum(s);
    if ((tid & 31) == 0) sh[tid >> 5] = s;
    __syncthreads();
    s = sh[tid & 7];
    #pragma unroll
    for (int o = 4; o; o >>= 1) s += __shfl_xor_sync(0xffffffffu, s, o);
    float inv = 1.f / s;
    #pragma unroll
    for (int j = 0; j < 4; j++) {
        v[j].x *= inv; v[j].y *= inv; v[j].z *= inv; v[j].w *= inv;
        p[tid + 256 * j] = v[j];
    }
}

__global__ void softmax256(float* __restrict__ data) {
    __shared__ float sh[8];
    float* p = data + (size_t)blockIdx.x * 256;
    int tid = threadIdx.x;
    float v = p[tid];
    float m = warpMax(v);
    if ((tid & 31) == 0) sh[tid >> 5] = m;
    __syncthreads();
    m = sh[tid & 7];
    #pragma unroll
    for (int o = 4; o; o >>= 1) m = fmaxf(m, __shfl_xor_sync(0xffffffffu, m, o));
    __syncthreads();
    float e = __expf(v - m);
    float s = warpSum(e);
    if ((tid & 31) == 0) sh[tid >> 5] = s;
    __syncthreads();
    s = sh[tid & 7];
    #pragma unroll
    for (int o = 4; o; o >>= 1) s += __shfl_xor_sync(0xffffffffu, s, o);
    p[tid] = e / s;
}

// ---------------- BN (train-mode batch stats) + ReLU ----------------
__global__ void bnstats(const float* __restrict__ y, float* __restrict__ meanp,
                        float* __restrict__ rstdp) {
    __shared__ float sh[16];
    int o = blockIdx.x, tid = threadIdx.x;
    float s = 0.f, sq = 0.f;
    for (int b = 0; b < 4; b++) {
        const float4* p = (const float4*)(y + ((size_t)b * 256 + o) * 4096);
        for (int i = tid; i < 1024; i += 256) {
            float4 v = p[i];
            s += v.x + v.y + v.z + v.w;
            sq += v.x * v.x + v.y * v.y + v.z * v.z + v.w * v.w;
        }
    }
    s = warpSum(s); sq = warpSum(sq);
    if ((tid & 31) == 0) { sh[tid >> 5] = s; sh[8 + (tid >> 5)] = sq; }
    __syncthreads();
    if (tid == 0) {
        float S = 0.f, SQ = 0.f;
        for (int i = 0; i < 8; i++) { S += sh[i]; SQ += sh[8 + i]; }
        float mean = S / 16384.f;
        float var = SQ / 16384.f - mean * mean;
        meanp[o] = mean;
        rstdp[o] = rsqrtf(var + 1e-5f);
    }
}

__global__ void bnapply(const float* __restrict__ y, const float* __restrict__ gam,
                        const float* __restrict__ bet, const float* __restrict__ meanp,
                        const float* __restrict__ rstdp, float* __restrict__ out) {
    size_t i = (size_t)blockIdx.x * 256 + threadIdx.x;  // float4 index
    int o = (int)((i >> 10) & 255);
    float mu = meanp[o], rs = rstdp[o], g = gam[o], be = bet[o];
    float4 v = ((const float4*)y)[i];
    float4 r;
    r.x = fmaxf(0.f, fmaf((v.x - mu) * rs, g, be));
    r.y = fmaxf(0.f, fmaf((v.y - mu) * rs, g, be));
    r.z = fmaxf(0.f, fmaf((v.z - mu) * rs, g, be));
    r.w = fmaxf(0.f, fmaf((v.w - mu) * rs, g, be));
    ((float4*)out)[i] = r;
}

// ---------------- launcher ----------------
extern "C" void kernel_launch(void* const* d_in, const int* in_sizes, int n_in,
                              void* d_out, int out_size) {
    const float* x   = (const float*)d_in[0];
    const float* wq  = (const float*)d_in[1];
    const float* bq  = (const float*)d_in[2];
    const float* wk  = (const float*)d_in[3];
    const float* bk  = (const float*)d_in[4];
    const float* wv  = (const float*)d_in[5];
    const float* bv  = (const float*)d_in[6];
    const float* gpa = (const float*)d_in[7];
    const float* gca = (const float*)d_in[8];
    const float* wf  = (const float*)d_in[9];
    const float* bng = (const float*)d_in[10];
    const float* bnb = (const float*)d_in[11];
    float* out = (float*)d_out;

    float *q, *k, *v, *attn, *cat, *cattn, *y, *mean, *rstd;
    cudaGetSymbolAddress((void**)&q, g_q);
    cudaGetSymbolAddress((void**)&k, g_k);
    cudaGetSymbolAddress((void**)&v, g_v);
    cudaGetSymbolAddress((void**)&attn, g_attn);
    cudaGetSymbolAddress((void**)&cat, g_cat);
    cudaGetSymbolAddress((void**)&cattn, g_cattn);
    cudaGetSymbolAddress((void**)&y, g_y);
    cudaGetSymbolAddress((void**)&mean, g_mean);
    cudaGetSymbolAddress((void**)&rstd, g_rstd);

    cudaFuncSetAttribute(pa_mma, cudaFuncAttributeMaxDynamicSharedMemorySize,
                         PA_SMEM_BYTES);
    cudaFuncSetAttribute(conv_mma, cudaFuncAttributeMaxDynamicSharedMemorySize,
                         CV_SMEM_BYTES);

    dim3 blk(256);
    long sx = (long)C_ * N_;
    long sqk = (long)CQ_ * N_;
    long sattn = (long)N_ * N_;
    long scat = (long)2 * C_ * N_;

    // q, k, v projections (1x1 convs as GEMMs)
    gemm_nn_k<<<dim3(64, 1, 4), blk>>>(wq, x, q, CQ_, N_, C_, 0, bq, nullptr, nullptr,
                                       0, sx, sqk, 0);
    gemm_nn_k<<<dim3(64, 1, 4), blk>>>(wk, x, k, CQ_, N_, C_, 0, bk, nullptr, nullptr,
                                       0, sx, sqk, 0);
    gemm_nn_k<<<dim3(64, 4, 4), blk>>>(wv, x, v, C_, N_, C_, 0, bv, nullptr, nullptr,
                                       0, sx, sx, 0);
    // logits[i][j] = sum_d q[d][i] k[d][j]
    gemm_tn_k<<<dim3(64, 64, 4), blk>>>(q, k, attn, N_, N_, CQ_, 2, nullptr, nullptr,
                                        nullptr, sqk, sqk, sattn, 0);
    softmax4096<<<B_ * N_, 256>>>(attn);
    // PA on tensor cores (tf32 mma.sync): cat[:,0:256] = gamma_pa * V @ attn^T + x
    pa_mma<<<dim3(32, 2, 4), blk, PA_SMEM_BYTES>>>(v, attn, x, gpa, cat);
    // channel logits[i][j] = sum_n x[i][n] x[j][n]
    gemm_nt_k<<<dim3(4, 4, 4), blk>>>(x, x, cattn, C_, C_, N_, 2, nullptr, nullptr,
                                      nullptr, sx, sx, (long)C_ * C_, 0);
    softmax256<<<B_ * C_, 256>>>(cattn);
    // ca -> cat[:, 256:512]
    gemm_nn_k<<<dim3(64, 4, 4), blk>>>(cattn, x, cat + (size_t)C_ * N_, C_, N_, C_, 1,
                                       nullptr, gca, x, (long)C_ * C_, sx, scat, sx);
    // 3x3 conv 512->256 on tensor cores (implicit GEMM)
    conv_mma<<<dim3(32, 2, 4), blk, CV_SMEM_BYTES>>>(cat, wf, y);
    // BN train-mode + ReLU
    bnstats<<<256, 256>>>(y, mean, rstd);
    bnapply<<<4096, 256>>>(y, bng, bnb, mean, rstd, out);
}